// round 1
// baseline (speedup 1.0000x reference)
#include <cuda_runtime.h>
#include <math.h>

#define BB 2
#define NN 2048
#define CC 64
#define NK 9
#define KC 576            // NK * CC

#define R2f     0.01f
#define PRUNE2  0.0292f   // (0.1 + 0.0707107)^2 = 0.0291421..., with margin
#define DILf    0.05f
#define FULLM   0xffffffffu

// knorm = 315 / (64 * pi * R^9), R = 0.1
#define KNORMf ((float)(315.0 / (64.0 * 3.14159265358979323846 * 1e-9)))

// ---------------- scratch (static device globals; no runtime allocation) ---
__device__ float g_coef[BB * NN];              // 1/(invmass*density)
__device__ float g_dcoefT[BB * NN * CC];       // [b][j][c]
__device__ float g_Wr[CC * KC];                // [o][k*64 + c]  (reordered weight)
__device__ float g_field[BB * NN * KC];        // [b*N+i][k*64 + c]

// ---------------- prep 1: coef + weight reorder ----------------------------
__global__ void prep1_kernel(const float* __restrict__ locs,
                             const float* __restrict__ density,
                             const float* __restrict__ weight) {
    int idx = blockIdx.x * blockDim.x + threadIdx.x;
    if (idx < BB * NN) {
        float im  = locs[idx * 3 + 2];
        float den = density[idx];
        g_coef[idx] = 1.0f / (im * den);
    }
    if (idx < CC * CC * NK) {
        int o = idx / (CC * NK);
        int r = idx - o * (CC * NK);
        int c = r / NK;
        int k = r - c * NK;
        g_Wr[o * KC + k * CC + c] = weight[idx];
    }
}

// ---------------- prep 2: transpose data -> dcoefT with coef ---------------
__global__ void prep2_kernel(const float* __restrict__ data) {
    __shared__ float s[32][33];
    int jt = blockIdx.x;      // 0..63
    int ct = blockIdx.y;      // 0..1
    int b  = blockIdx.z;      // 0..1
    int tx = threadIdx.x, ty = threadIdx.y;

    int c = ct * 32 + ty;
    int j = jt * 32 + tx;
    s[ty][tx] = data[(b * CC + c) * NN + j];
    __syncthreads();

    int j2 = jt * 32 + ty;
    int c2 = ct * 32 + tx;
    g_dcoefT[(b * NN + j2) * CC + c2] = s[tx][ty] * g_coef[b * NN + j2];
}

// ---------------- main: sparse SPH gather, warp per output particle -------
__device__ __forceinline__ float wfun(float t) {
    t = fmaxf(t, 0.0f);
    return (t * t) * (t * KNORMf);
}

__global__ __launch_bounds__(256) void convsp_main_kernel(
        const float* __restrict__ locs) {
    __shared__ float2 posS[NN];

    int b  = blockIdx.x >> 8;            // 512 blocks: 256 per batch
    int i0 = (blockIdx.x & 255) * 8;
    int tid = threadIdx.x;

    for (int t = tid; t < NN; t += 256) {
        const float* lp = locs + (size_t)(b * NN + t) * 3;
        posS[t] = make_float2(lp[0], lp[1]);
    }
    __syncthreads();

    int warp = tid >> 5;
    int lane = tid & 31;
    int i = i0 + warp;

    float xi = posS[i].x;
    float yi = posS[i].y;

    float2 acc0 = make_float2(0.f, 0.f), acc1 = acc0, acc2 = acc0;
    float2 acc3 = acc0, acc4 = acc0, acc5 = acc0;
    float2 acc6 = acc0, acc7 = acc0, acc8 = acc0;

    const float2* dcT = reinterpret_cast<const float2*>(g_dcoefT)
                        + ((size_t)b * NN * 32 + lane);

    for (int j0 = 0; j0 < NN; j0 += 32) {
        float2 pj = posS[j0 + lane];
        float dx = xi - pj.x;
        float dy = yi - pj.y;
        float d2b = dx * dx + dy * dy;

        if (!__any_sync(FULLM, d2b < PRUNE2)) continue;

        float bxm = dx - DILf, bxp = dx + DILf;
        float bym = dy - DILf, byp = dy + DILf;
        float rx0 = R2f - bxm * bxm;
        float rx1 = R2f - dx * dx;
        float rx2 = R2f - bxp * bxp;
        float ay0 = bym * bym;
        float ay1 = dy * dy;
        float ay2 = byp * byp;

        float w0 = wfun(rx0 - ay0);
        float w1 = wfun(rx0 - ay1);
        float w2 = wfun(rx0 - ay2);
        float w3 = wfun(rx1 - ay0);
        float w4 = wfun(rx1 - ay1);
        float w5 = wfun(rx1 - ay2);
        float w6 = wfun(rx2 - ay0);
        float w7 = wfun(rx2 - ay1);
        float w8 = wfun(rx2 - ay2);

        bool anyw = (fmaxf(rx0, fmaxf(rx1, rx2)) >
                     fminf(ay0, fminf(ay1, ay2)));

        unsigned m = __ballot_sync(FULLM, anyw);
        while (m) {
            int src = __ffs((int)m) - 1;
            m &= m - 1;
            float2 dc = __ldg(&dcT[(size_t)(j0 + src) << 5]);
            float s;
            s = __shfl_sync(FULLM, w0, src);
            acc0.x = fmaf(s, dc.x, acc0.x); acc0.y = fmaf(s, dc.y, acc0.y);
            s = __shfl_sync(FULLM, w1, src);
            acc1.x = fmaf(s, dc.x, acc1.x); acc1.y = fmaf(s, dc.y, acc1.y);
            s = __shfl_sync(FULLM, w2, src);
            acc2.x = fmaf(s, dc.x, acc2.x); acc2.y = fmaf(s, dc.y, acc2.y);
            s = __shfl_sync(FULLM, w3, src);
            acc3.x = fmaf(s, dc.x, acc3.x); acc3.y = fmaf(s, dc.y, acc3.y);
            s = __shfl_sync(FULLM, w4, src);
            acc4.x = fmaf(s, dc.x, acc4.x); acc4.y = fmaf(s, dc.y, acc4.y);
            s = __shfl_sync(FULLM, w5, src);
            acc5.x = fmaf(s, dc.x, acc5.x); acc5.y = fmaf(s, dc.y, acc5.y);
            s = __shfl_sync(FULLM, w6, src);
            acc6.x = fmaf(s, dc.x, acc6.x); acc6.y = fmaf(s, dc.y, acc6.y);
            s = __shfl_sync(FULLM, w7, src);
            acc7.x = fmaf(s, dc.x, acc7.x); acc7.y = fmaf(s, dc.y, acc7.y);
            s = __shfl_sync(FULLM, w8, src);
            acc8.x = fmaf(s, dc.x, acc8.x); acc8.y = fmaf(s, dc.y, acc8.y);
        }
    }

    float* f = g_field + (size_t)(b * NN + i) * KC + 2 * lane;
    *reinterpret_cast<float2*>(f + 0 * CC) = acc0;
    *reinterpret_cast<float2*>(f + 1 * CC) = acc1;
    *reinterpret_cast<float2*>(f + 2 * CC) = acc2;
    *reinterpret_cast<float2*>(f + 3 * CC) = acc3;
    *reinterpret_cast<float2*>(f + 4 * CC) = acc4;
    *reinterpret_cast<float2*>(f + 5 * CC) = acc5;
    *reinterpret_cast<float2*>(f + 6 * CC) = acc6;
    *reinterpret_cast<float2*>(f + 7 * CC) = acc7;
    *reinterpret_cast<float2*>(f + 8 * CC) = acc8;
}

// ---------------- final: out[b,o,i] = bias[o] + Wr[o,:] . field[b,i,:] ----
__global__ __launch_bounds__(256) void wgemm_kernel(
        const float* __restrict__ bias, float* __restrict__ out) {
    __shared__ float Ws[64][68];   // [kk][o], pad 68 (16B-aligned rows)
    __shared__ float Fs[64][36];   // [kk][i], i-tile = 32

    int b  = blockIdx.x >> 6;          // 128 blocks: 64 i-tiles per batch
    int i0 = (blockIdx.x & 63) * 32;
    int tid = threadIdx.x;

    int oq = (tid & 15) * 4;
    int iq = (tid >> 4) * 2;

    float a00 = 0.f, a01 = 0.f, a10 = 0.f, a11 = 0.f;
    float a20 = 0.f, a21 = 0.f, a30 = 0.f, a31 = 0.f;

    for (int kc0 = 0; kc0 < KC; kc0 += 64) {
        #pragma unroll
        for (int s = 0; s < 16; s++) {
            int l = tid + s * 256;
            int o  = l >> 6;
            int kk = l & 63;
            Ws[kk][o] = g_Wr[o * KC + kc0 + kk];
        }
        #pragma unroll
        for (int s = 0; s < 8; s++) {
            int l = tid + s * 256;
            int ii = l >> 6;
            int kk = l & 63;
            Fs[kk][ii] = g_field[(size_t)(b * NN + i0 + ii) * KC + kc0 + kk];
        }
        __syncthreads();

        #pragma unroll
        for (int kk = 0; kk < 64; kk++) {
            float4 a = *reinterpret_cast<const float4*>(&Ws[kk][oq]);
            float2 fv = *reinterpret_cast<const float2*>(&Fs[kk][iq]);
            a00 = fmaf(a.x, fv.x, a00); a01 = fmaf(a.x, fv.y, a01);
            a10 = fmaf(a.y, fv.x, a10); a11 = fmaf(a.y, fv.y, a11);
            a20 = fmaf(a.z, fv.x, a20); a21 = fmaf(a.z, fv.y, a21);
            a30 = fmaf(a.w, fv.x, a30); a31 = fmaf(a.w, fv.y, a31);
        }
        __syncthreads();
    }

    float b0 = bias[oq + 0], b1 = bias[oq + 1];
    float b2 = bias[oq + 2], b3 = bias[oq + 3];
    size_t base = (size_t)(b * CC) * NN + i0 + iq;
    *reinterpret_cast<float2*>(&out[base + (size_t)(oq + 0) * NN]) =
        make_float2(b0 + a00, b0 + a01);
    *reinterpret_cast<float2*>(&out[base + (size_t)(oq + 1) * NN]) =
        make_float2(b1 + a10, b1 + a11);
    *reinterpret_cast<float2*>(&out[base + (size_t)(oq + 2) * NN]) =
        make_float2(b2 + a20, b2 + a21);
    *reinterpret_cast<float2*>(&out[base + (size_t)(oq + 3) * NN]) =
        make_float2(b3 + a30, b3 + a31);
}

// ---------------- launcher -------------------------------------------------
extern "C" void kernel_launch(void* const* d_in, const int* in_sizes, int n_in,
                              void* d_out, int out_size) {
    // Bind inputs by (unique) element counts for robustness:
    // locs 2*2048*3=12288, data 2*64*2048=262144, density 2*2048=4096,
    // weight 64*64*9=36864, bias 64.
    const float* locs = nullptr;
    const float* data = nullptr;
    const float* density = nullptr;
    const float* weight = nullptr;
    const float* bias = nullptr;
    for (int idx = 0; idx < n_in; idx++) {
        switch (in_sizes[idx]) {
            case 12288:  locs    = (const float*)d_in[idx]; break;
            case 262144: data    = (const float*)d_in[idx]; break;
            case 4096:   density = (const float*)d_in[idx]; break;
            case 36864:  weight  = (const float*)d_in[idx]; break;
            case 64:     bias    = (const float*)d_in[idx]; break;
            default: break;
        }
    }
    float* out = (float*)d_out;

    prep1_kernel<<<144, 256>>>(locs, density, weight);
    prep2_kernel<<<dim3(64, 2, 2), dim3(32, 32)>>>(data);
    convsp_main_kernel<<<512, 256>>>(locs);
    wgemm_kernel<<<128, 256>>>(bias, out);
}